// round 6
// baseline (speedup 1.0000x reference)
#include <cuda_runtime.h>
#include <cuda_bf16.h>
#include <math.h>
#include <stdint.h>

// Problem constants
#define BATCH 4
#define SEQ   128
#define HID   256
#define CNUM  6
#define EMBD  400
#define G4    1024
#define D2    512
#define BL    512          // BATCH*SEQ

// ---------------- scratch offsets (floats) ----------------
#define OFF_EMB   0u               // 512*400
#define OFF_XGF   204800u          // 512*1024
#define OFF_XGB   729088u          // 512*1024
#define OFF_CTX   1253376u         // 512*512
#define OFF_Q     1515520u         // 512*512
#define OFF_K     1777664u         // 512*512
#define OFF_S     2039808u         // 4*128*128
#define OFF_CTX2  2105344u         // 512*512
#define OFF_X0    2367488u         // 512*6
#define OFF_Y0    2370560u
#define OFF_LM0   2373632u
#define OFF_FA1   2376704u         // 512*1024
#define OFF_FB1   2900992u         // 512*1024
#define OFF_X1    3425280u
#define OFF_Y1    3428352u
#define OFF_LM1   3431424u
#define OFF_FA2   3434496u         // 512*1024
#define OFF_FB2   3958784u         // 512*1024
#define OFF_X2    4483072u
#define OFF_Y2    4486144u
#define OFF_C1    4489216u         // 1024
#define OFF_C2    4490240u         // 1024
#define OFF_CB1   4491264u         // 8
#define OFF_CB2   4491272u         // 8
#define OFF_WT    4491280u         // 18*1024 packed extra feat_w cols
#define SCRATCH_FLOATS 4509712u

__device__ __align__(16) float g_scratch[SCRATCH_FLOATS];
__device__ unsigned int g_bar[8];

typedef unsigned long long u64;

// ---------------- packed f32x2 helpers (Blackwell FFMA2) ----------------
__device__ __forceinline__ void fma2(u64& d, u64 a, u64 b) {
    asm("fma.rn.f32x2 %0, %1, %2, %0;" : "+l"(d) : "l"(a), "l"(b));
}
__device__ __forceinline__ u64 dupf(float v) {
    u64 r; unsigned u = __float_as_uint(v);
    asm("mov.b64 %0, {%1, %1};" : "=l"(r) : "r"(u));
    return r;
}
__device__ __forceinline__ float2 unpk(u64 v) {
    unsigned lo, hi;
    asm("mov.b64 {%0, %1}, %2;" : "=r"(lo), "=r"(hi) : "l"(v));
    return make_float2(__uint_as_float(lo), __uint_as_float(hi));
}
union F4U { float4 f; u64 u[2]; };
union F2U { float2 f; u64 u; };

__device__ __forceinline__ float sigf(float x) { return 1.f / (1.f + __expf(-x)); }

// ---------------- embedding (+ barrier zero fused) ----------------
__global__ void k_embed(const int* __restrict__ tok, const float* __restrict__ mask,
                        const float* __restrict__ gen, const float* __restrict__ dom,
                        float* __restrict__ emb, unsigned int* __restrict__ bar) {
    if (blockIdx.x == 0 && threadIdx.x < 8) bar[threadIdx.x] = 0u;
    int idx = blockIdx.x * blockDim.x + threadIdx.x;
    if (idx >= BL * EMBD) return;
    int bl = idx / EMBD, d = idx - bl * EMBD;
    int t = tok[bl];
    float v = (d < 300) ? gen[(size_t)t * 300 + d] : dom[(size_t)t * 100 + (d - 300)];
    emb[idx] = v * mask[bl];
}

// ---------------- GEMM NT core (device), f32x2 inner product ----------------
// Optional fused rank-12 epilogue: C[m,n] (+)= sum_c U[m,c]*WT[offU+c][n] + V[m,c]*WT[12+c][n]
__device__ __forceinline__ void gemm_nt_body(
    const float* __restrict__ A, int lda,
    const float* __restrict__ B, int ldb,
    float* __restrict__ C, int ldc, int K,
    const float* __restrict__ b0, const float* __restrict__ b1,
    const float* __restrict__ U, const float* __restrict__ V,
    const float* __restrict__ WT, int offU) {
    __shared__ __align__(16) float As[16][68];
    __shared__ __align__(16) float Bs[16][68];
    const int tx = threadIdx.x, ty = threadIdx.y;
    const int m0 = blockIdx.y * 64, n0 = blockIdx.x * 64;
    u64 acc2[2][4];
#pragma unroll
    for (int p = 0; p < 2; p++)
#pragma unroll
        for (int j = 0; j < 4; j++) acc2[p][j] = 0ull;

    for (int k0 = 0; k0 < K; k0 += 16) {
#pragma unroll
        for (int r = 0; r < 4; r++) {
            int m = ty + r * 16;
            As[tx][m] = A[(size_t)(m0 + m) * lda + k0 + tx];
            Bs[tx][m] = B[(size_t)(n0 + m) * ldb + k0 + tx];
        }
        __syncthreads();
#pragma unroll
        for (int k = 0; k < 16; k++) {
            const ulonglong2 a2 = *(const ulonglong2*)(&As[k][ty * 4]);
            const float4 b4 = *(const float4*)(&Bs[k][tx * 4]);
            u64 bd0 = dupf(b4.x), bd1 = dupf(b4.y), bd2 = dupf(b4.z), bd3 = dupf(b4.w);
            fma2(acc2[0][0], a2.x, bd0); fma2(acc2[0][1], a2.x, bd1);
            fma2(acc2[0][2], a2.x, bd2); fma2(acc2[0][3], a2.x, bd3);
            fma2(acc2[1][0], a2.y, bd0); fma2(acc2[1][1], a2.y, bd1);
            fma2(acc2[1][2], a2.y, bd2); fma2(acc2[1][3], a2.y, bd3);
        }
        __syncthreads();
    }
#pragma unroll
    for (int p = 0; p < 2; p++) {
#pragma unroll
        for (int j = 0; j < 4; j++) {
            float2 v = unpk(acc2[p][j]);
            int n = n0 + tx * 4 + j;
            int m = m0 + ty * 4 + 2 * p;
            float e0 = (b0 ? b0[n] : 0.f) + (b1 ? b1[n] : 0.f);
            float e1 = e0;
            if (WT) {
#pragma unroll
                for (int c = 0; c < CNUM; c++) {
                    float wu = WT[(size_t)(offU + c) * 1024 + n];
                    float wv = WT[(size_t)(12 + c) * 1024 + n];
                    e0 += U[(size_t)m * CNUM + c] * wu + V[(size_t)m * CNUM + c] * wv;
                    e1 += U[(size_t)(m + 1) * CNUM + c] * wu + V[(size_t)(m + 1) * CNUM + c] * wv;
                }
            }
            C[(size_t)m * ldc + n]       = v.x + e0;
            C[(size_t)(m + 1) * ldc + n] = v.y + e1;
        }
    }
}

// strided-z variant
__global__ void k_gemm_nt(const float* __restrict__ A, int lda, long long sA,
                          const float* __restrict__ B, int ldb, long long sB,
                          float* __restrict__ C, int ldc, long long sC,
                          int K, const float* __restrict__ b0, const float* __restrict__ b1) {
    gemm_nt_body(A + blockIdx.z * sA, lda, B + blockIdx.z * sB, ldb,
                 C + blockIdx.z * sC, ldc, K, b0, b1,
                 nullptr, nullptr, nullptr, 0);
}

// strided-z variant with fused rank-12 epilogue (z=0: offU=0,V=V0 ; z=1: offU=6,V=V1)
__global__ void k_gemm_nt_r12(const float* __restrict__ A, int lda, long long sA,
                              const float* __restrict__ B, int ldb, long long sB,
                              float* __restrict__ C, int ldc, long long sC, int K,
                              const float* __restrict__ U,
                              const float* __restrict__ V0, const float* __restrict__ V1,
                              const float* __restrict__ WT) {
    int z = blockIdx.z;
    gemm_nt_body(A + z * sA, lda, B + z * sB, ldb, C + z * sC, ldc, K,
                 nullptr, nullptr, U, z ? V1 : V0, WT, z ? 6 : 0);
}

// paired-pointer variant (z selects independent operand sets)
__global__ void k_gemm_nt2(const float* __restrict__ A0, const float* __restrict__ A1, int lda,
                           const float* __restrict__ B0, const float* __restrict__ B1, int ldb,
                           float* __restrict__ C0, float* __restrict__ C1, int ldc, int K,
                           const float* __restrict__ p00, const float* __restrict__ p01,
                           const float* __restrict__ p10, const float* __restrict__ p11) {
    if (blockIdx.z == 0)
        gemm_nt_body(A0, lda, B0, ldb, C0, ldc, K, p00, p01, nullptr, nullptr, nullptr, 0);
    else
        gemm_nt_body(A1, lda, B1, ldb, C1, ldc, K, p10, p11, nullptr, nullptr, nullptr, 0);
}

// ---------------- GEMM NN: C[M,N] = A[M,K] @ B[K,N] (+D), f32x2 inner ----------------
__global__ void k_gemm_nn(const float* __restrict__ A, int lda, long long sA,
                          const float* __restrict__ B, int ldb, long long sB,
                          float* __restrict__ C, int ldc, long long sC,
                          int K, const float* __restrict__ D, int ldd, long long sD) {
    A += blockIdx.z * sA; B += blockIdx.z * sB; C += blockIdx.z * sC;
    if (D) D += blockIdx.z * sD;
    __shared__ __align__(16) float As[16][68];
    __shared__ __align__(16) float Bs[16][68];
    const int tx = threadIdx.x, ty = threadIdx.y;
    const int t = ty * 16 + tx;
    const int m0 = blockIdx.y * 64, n0 = blockIdx.x * 64;
    const int bn = t & 63, bk = t >> 6;
    u64 acc2[2][4];
#pragma unroll
    for (int p = 0; p < 2; p++)
#pragma unroll
        for (int j = 0; j < 4; j++) acc2[p][j] = 0ull;

    for (int k0 = 0; k0 < K; k0 += 16) {
#pragma unroll
        for (int r = 0; r < 4; r++) {
            int m = ty + r * 16;
            As[tx][m] = A[(size_t)(m0 + m) * lda + k0 + tx];
            int kk = bk + r * 4;
            Bs[kk][bn] = B[(size_t)(k0 + kk) * ldb + n0 + bn];
        }
        __syncthreads();
#pragma unroll
        for (int k = 0; k < 16; k++) {
            const ulonglong2 a2 = *(const ulonglong2*)(&As[k][ty * 4]);
            const float4 b4 = *(const float4*)(&Bs[k][tx * 4]);
            u64 bd0 = dupf(b4.x), bd1 = dupf(b4.y), bd2 = dupf(b4.z), bd3 = dupf(b4.w);
            fma2(acc2[0][0], a2.x, bd0); fma2(acc2[0][1], a2.x, bd1);
            fma2(acc2[0][2], a2.x, bd2); fma2(acc2[0][3], a2.x, bd3);
            fma2(acc2[1][0], a2.y, bd0); fma2(acc2[1][1], a2.y, bd1);
            fma2(acc2[1][2], a2.y, bd2); fma2(acc2[1][3], a2.y, bd3);
        }
        __syncthreads();
    }
#pragma unroll
    for (int p = 0; p < 2; p++) {
#pragma unroll
        for (int j = 0; j < 4; j++) {
            float2 v = unpk(acc2[p][j]);
            int n = n0 + tx * 4 + j;
            int m = m0 + ty * 4 + 2 * p;
            float d0 = D ? D[(size_t)m * ldd + n] : 0.f;
            float d1 = D ? D[(size_t)(m + 1) * ldd + n] : 0.f;
            C[(size_t)m * ldc + n]       = v.x + d0;
            C[(size_t)(m + 1) * ldc + n] = v.y + d1;
        }
    }
}

// ---------------- BiLSTM recurrence ----------------
// 64 blocks = 8 groups (b,dir) x 8 slices; 128 threads = 4 gate types x 32 cells.
__global__ void k_lstm(const float* __restrict__ xgf, const float* __restrict__ xgb,
                       const float* __restrict__ whhf, const float* __restrict__ whhb,
                       float* __restrict__ ctx, unsigned int* __restrict__ bar) {
    const int bx = blockIdx.x;
    const int group = bx >> 3, slice = bx & 7;
    const int b = group >> 1, dir = group & 1;
    const float* xg  = dir ? xgb : xgf;
    const float* whh = dir ? whhb : whhf;
    const int tid = threadIdx.x;
    const int type = tid >> 5, lane = tid & 31;
    const int cell = slice * 32 + lane;
    const int row = type * 256 + cell;
    const float* wr = whh + (size_t)row * 256;
    __shared__ float gs[128];
    float c_reg = 0.f;
    volatile unsigned int* cnt = bar + group;

    for (int s = 0; s < SEQ; s++) {
        const int t = dir ? (SEQ - 1 - s) : s;
        float acc = xg[(size_t)(b * SEQ + t) * G4 + row];
        if (s > 0) {
            const int tp = dir ? (t + 1) : (t - 1);
            const float* hp = ctx + (size_t)(b * SEQ + tp) * D2 + dir * HID;
            u64 a0 = 0ull, a1 = 0ull, a2 = 0ull, a3 = 0ull;
#pragma unroll
            for (int k = 0; k < 256; k += 8) {
                F4U w0, w1, h0, h1;
                w0.f = *(const float4*)(wr + k);
                w1.f = *(const float4*)(wr + k + 4);
                h0.f = __ldcg((const float4*)(hp + k));
                h1.f = __ldcg((const float4*)(hp + k + 4));
                fma2(a0, w0.u[0], h0.u[0]);
                fma2(a1, w0.u[1], h0.u[1]);
                fma2(a2, w1.u[0], h1.u[0]);
                fma2(a3, w1.u[1], h1.u[1]);
            }
            float2 r0 = unpk(a0), r1 = unpk(a1), r2 = unpk(a2), r3 = unpk(a3);
            acc += ((r0.x + r0.y) + (r1.x + r1.y)) + ((r2.x + r2.y) + (r3.x + r3.y));
        }
        gs[tid] = acc;
        __syncthreads();
        if (type == 0) {
            float gi = gs[lane], gf = gs[32 + lane], gg = gs[64 + lane], go = gs[96 + lane];
            c_reg = sigf(gf) * c_reg + sigf(gi) * tanhf(gg);
            float h = sigf(go) * tanhf(c_reg);
            __stcg(&ctx[(size_t)(b * SEQ + t) * D2 + dir * HID + cell], h);
            __threadfence();             // each writer publishes ITS OWN store
        }
        __syncthreads();                 // all fenced stores complete block-wide
        if (tid == 0) {
            atomicAdd(bar + group, 1u);
            unsigned int target = 8u * (unsigned)(s + 1);
            while (*cnt < target) { }
            __threadfence();
        }
        __syncthreads();
    }
}

// ---------------- softmax over keys (row-wise, with mask) ----------------
__global__ void k_softmax(float* __restrict__ S, const float* __restrict__ mask) {
    int rowid = blockIdx.x;              // b*128 + i
    int b = rowid >> 7;
    int j = threadIdx.x;
    __shared__ float sh[128];
    float* row = S + (size_t)rowid * 128;
    float v = row[j];
    if (mask[b * 128 + j] <= 0.f) v = -1e30f;
    sh[j] = v; __syncthreads();
    for (int off = 64; off > 0; off >>= 1) {
        if (j < off) sh[j] = fmaxf(sh[j], sh[j + off]);
        __syncthreads();
    }
    float mx = sh[0]; __syncthreads();
    float e = __expf(v - mx);
    sh[j] = e; __syncthreads();
    for (int off = 64; off > 0; off >>= 1) {
        if (j < off) sh[j] += sh[j + off];
        __syncthreads();
    }
    row[j] = e / sh[0];
}

// ---------------- fused small NT gemm pair: C{0,1}[M,6] = A{0,1} @ B{0,1}^T ----------------
__global__ void k_small_nt2(const float* __restrict__ A0, const float* __restrict__ A1, int lda,
                            const float* __restrict__ B0, const float* __restrict__ B1, int ldb,
                            int K, float* __restrict__ C0, float* __restrict__ C1) {
    int z = blockIdx.y;
    const float* A = z ? A1 : A0;
    const float* B = z ? B1 : B0;
    float* C = z ? C1 : C0;
    int r = blockIdx.x;
    int c = threadIdx.x >> 5, lane = threadIdx.x & 31;
    if (c >= CNUM) return;
    const float* a = A + (size_t)r * lda;
    const float* w = B + (size_t)c * ldb;
    u64 acc0 = 0ull, acc1 = 0ull;
    for (int k = lane * 2; k < K; k += 128) {
        F2U av, wv; av.f = *(const float2*)(a + k); wv.f = *(const float2*)(w + k);
        fma2(acc0, av.u, wv.u);
        int k2 = k + 64;
        if (k2 < K) {
            F2U av2, wv2; av2.f = *(const float2*)(a + k2); wv2.f = *(const float2*)(w + k2);
            fma2(acc1, av2.u, wv2.u);
        }
    }
    float2 r0 = unpk(acc0), r1 = unpk(acc1);
    float s = (r0.x + r0.y) + (r1.x + r1.y);
#pragma unroll
    for (int off = 16; off > 0; off >>= 1) s += __shfl_xor_sync(0xffffffffu, s, off);
    if (lane == 0) C[(size_t)r * CNUM + c] = s;
}

// ---------------- lm via prefix/suffix max, with inline cb computation ----------------
// cb[c] = cls_b[c] + (vecC ? dot(vecC, cls_w[c,:1024]) : 0); block b==0 publishes CBout.
// lm[b,l,c] = max( prefmax_{i<=l}X + Y[l] + cb, X[l] + sufmax_{j>=l}Y + cb, 0 )
__global__ void k_lm(const float* __restrict__ X, const float* __restrict__ Y,
                     const float* __restrict__ vecC, const float* __restrict__ cls_w,
                     const float* __restrict__ cls_b,
                     float* __restrict__ LM, float* __restrict__ CBout) {
    int b = blockIdx.x / CNUM, c = blockIdx.x % CNUM;
    int l = threadIdx.x;
    __shared__ float px[128], sy[128], red[128];
    float cbv = cls_b[c];
    if (vecC) {
        const float* w = cls_w + (size_t)c * 1024;
        float partial = 0.f;
#pragma unroll
        for (int d = l; d < 1024; d += 128) partial += vecC[d] * w[d];
        red[l] = partial; __syncthreads();
        for (int off = 64; off > 0; off >>= 1) {
            if (l < off) red[l] += red[l + off];
            __syncthreads();
        }
        cbv += red[0];
        __syncthreads();
    }
    if (CBout && b == 0 && l == 0) CBout[c] = cbv;
    float x = X[(size_t)(b * 128 + l) * CNUM + c];
    float y = Y[(size_t)(b * 128 + l) * CNUM + c];
    px[l] = x; sy[l] = y;
    __syncthreads();
    for (int off = 1; off < 128; off <<= 1) {
        float pother = (l >= off) ? px[l - off] : -3e38f;
        float sother = (l + off < 128) ? sy[l + off] : -3e38f;
        float pmine = px[l], smine = sy[l];
        __syncthreads();
        px[l] = fmaxf(pmine, pother);
        sy[l] = fmaxf(smine, sother);
        __syncthreads();
    }
    float v = fmaxf(fmaxf(px[l] + y + cbv, x + sy[l] + cbv), 0.f);
    LM[(size_t)(b * 128 + l) * CNUM + c] = v;
}

// ---------------- packWT + const1 fused ----------------
// blocks 0..71: WT[c][o] = fw[o*1042 + 1024 + c]
// blocks 72..75: C1[o] = feat_b[o] + sum_c cls_b[c] * fw[o*1042 + 1036 + c]
__global__ void k_packWT_c1(const float* __restrict__ fw, float* __restrict__ WT,
                            const float* __restrict__ feat_b, const float* __restrict__ cls_b,
                            float* __restrict__ C1) {
    int bx = blockIdx.x;
    if (bx < 72) {
        int idx = bx * 256 + threadIdx.x;
        if (idx < 18 * 1024) {
            int c = idx >> 10, o = idx & 1023;
            WT[idx] = fw[(size_t)o * 1042 + 1024 + c];
        }
    } else {
        int o = (bx - 72) * 256 + threadIdx.x;
        float s = feat_b[o];
        const float* row = fw + (size_t)o * 1042 + 1036;
#pragma unroll
        for (int c = 0; c < CNUM; c++) s += cls_b[c] * row[c];
        C1[o] = s;
    }
}

// const2[o] = feat_b[o] + dot(C1, feat_w[o,0:1024]) + sum_c CB1[c]*Wp[o,c]
__global__ void k_const2(const float* __restrict__ C1, const float* __restrict__ fw,
                         const float* __restrict__ feat_b, const float* __restrict__ CB1,
                         const float* __restrict__ WT, float* __restrict__ C2) {
    int warp = threadIdx.x >> 5, lane = threadIdx.x & 31;
    int o = blockIdx.x * (blockDim.x >> 5) + warp;
    const float* w = fw + (size_t)o * 1042;
    float s = 0.f;
    for (int d = lane; d < 1024; d += 32) s += C1[d] * w[d];
#pragma unroll
    for (int off = 16; off > 0; off >>= 1) s += __shfl_xor_sync(0xffffffffu, s, off);
    if (lane == 0) {
        float v = feat_b[o] + s;
#pragma unroll
        for (int c = 0; c < CNUM; c++) v += CB1[c] * WT[(size_t)(12 + c) * 1024 + o];
        C2[o] = v;
    }
}

// cb[c] = cls_b[c] + dot(vec[0:1024], cls_w[c,:])
__global__ void k_cb(const float* __restrict__ vec, const float* __restrict__ cls_w,
                     const float* __restrict__ cls_b, float* __restrict__ CB) {
    int c = threadIdx.x >> 5, lane = threadIdx.x & 31;
    if (c >= CNUM) return;
    const float* w = cls_w + (size_t)c * 1024;
    float s = 0.f;
    for (int d = lane; d < 1024; d += 32) s += vec[d] * w[d];
#pragma unroll
    for (int off = 16; off > 0; off >>= 1) s += __shfl_xor_sync(0xffffffffu, s, off);
    if (lane == 0) CB[c] = cls_b[c] + s;
}

// ---------------- final separable write ----------------
__global__ void k_output(const float* __restrict__ X2, const float* __restrict__ Y2,
                         const float* __restrict__ CB2, float* __restrict__ out) {
    int idx = blockIdx.x * blockDim.x + threadIdx.x;
    if (idx >= BATCH * SEQ * SEQ * CNUM) return;
    int c = idx % CNUM;
    int j = (idx / CNUM) & 127;
    int i = (idx / (CNUM * SEQ)) & 127;
    int b = idx / (CNUM * SEQ * SEQ);
    out[idx] = X2[(size_t)(b * 128 + i) * CNUM + c] + Y2[(size_t)(b * 128 + j) * CNUM + c] + CB2[c];
}

// ---------------- launch ----------------
extern "C" void kernel_launch(void* const* d_in, const int* in_sizes, int n_in,
                              void* d_out, int out_size) {
    const int*   tok     = (const int*)  d_in[0];
    // d_in[1] = lengths (unused; all full length)
    const float* mask    = (const float*)d_in[2];
    const float* gen     = (const float*)d_in[3];
    const float* dom     = (const float*)d_in[4];
    const float* wih_f   = (const float*)d_in[5];
    const float* whh_f   = (const float*)d_in[6];
    const float* bih_f   = (const float*)d_in[7];
    const float* bhh_f   = (const float*)d_in[8];
    const float* wih_b   = (const float*)d_in[9];
    const float* whh_b   = (const float*)d_in[10];
    const float* bih_b   = (const float*)d_in[11];
    const float* bhh_b   = (const float*)d_in[12];
    const float* wq      = (const float*)d_in[13];
    const float* bq      = (const float*)d_in[14];
    const float* wk      = (const float*)d_in[15];
    const float* bk      = (const float*)d_in[16];
    const float* feat_w  = (const float*)d_in[17];
    const float* feat_b  = (const float*)d_in[18];
    const float* cls_w   = (const float*)d_in[19];
    const float* cls_b   = (const float*)d_in[20];
    float* out = (float*)d_out;

    float* sc = nullptr;
    unsigned int* bar = nullptr;
    cudaGetSymbolAddress((void**)&sc, g_scratch);
    cudaGetSymbolAddress((void**)&bar, g_bar);

    dim3 tb(16, 16);

    // 1. embedding (+bar zero)
    k_embed<<<(BL * EMBD + 255) / 256, 256>>>(tok, mask, gen, dom, sc + OFF_EMB, bar);

    // 2. xg = emb @ wih^T + bih + bhh   [512,1024], K=400  (f/b fused via z)
    k_gemm_nt2<<<dim3(16, 8, 2), tb>>>(sc + OFF_EMB, sc + OFF_EMB, EMBD,
                                       wih_f, wih_b, EMBD,
                                       sc + OFF_XGF, sc + OFF_XGB, G4, EMBD,
                                       bih_f, bhh_f, bih_b, bhh_b);

    // 3. BiLSTM -> ctx [512,512]
    k_lstm<<<64, 128>>>(sc + OFF_XGF, sc + OFF_XGB, whh_f, whh_b, sc + OFF_CTX, bar);

    // 4. attention projections (Q,K fused)
    k_gemm_nt2<<<dim3(8, 8, 2), tb>>>(sc + OFF_CTX, sc + OFF_CTX, D2,
                                      wq, wk, D2,
                                      sc + OFF_Q, sc + OFF_K, D2, D2,
                                      bq, nullptr, bk, nullptr);
    // 5. scores per batch
    k_gemm_nt<<<dim3(2, 2, 4), tb>>>(sc + OFF_Q, D2, 65536, sc + OFF_K, D2, 65536,
                                     sc + OFF_S, 128, 16384, D2, nullptr, nullptr);
    // 6. softmax
    k_softmax<<<BL, 128>>>(sc + OFF_S, mask);
    // 7. ctx2 = attn@ctx + ctx
    k_gemm_nn<<<dim3(8, 2, 4), tb>>>(sc + OFF_S, 128, 16384, sc + OFF_CTX, D2, 65536,
                                     sc + OFF_CTX2, D2, 65536, 128,
                                     sc + OFF_CTX, D2, 65536);

    // 8. hop 0 separable logits
    k_small_nt2<<<dim3(BL, 2), 192>>>(sc + OFF_CTX2, sc + OFF_CTX2, D2,
                                      cls_w, cls_w + 512, G4, D2,
                                      sc + OFF_X0, sc + OFF_Y0);
    // 9. lm0 (cb = cls_b directly)
    k_lm<<<BATCH * CNUM, 128>>>(sc + OFF_X0, sc + OFF_Y0, nullptr, cls_w, cls_b,
                                sc + OFF_LM0, nullptr);
    // 10. pack WT + const1
    k_packWT_c1<<<76, 256>>>(feat_w, sc + OFF_WT, feat_b, cls_b, sc + OFF_C1);

    // 11. hop 1: FA1 = ctx2@Wf[:, :512]^T + lm0@WTu + X0@WTp ; FB1 analog (rank12 fused)
    k_gemm_nt_r12<<<dim3(16, 8, 2), tb>>>(sc + OFF_CTX2, D2, 0,
                                          feat_w, 1042, 512,
                                          sc + OFF_FA1, G4, (long long)(OFF_FB1 - OFF_FA1),
                                          D2, sc + OFF_LM0, sc + OFF_X0, sc + OFF_Y0,
                                          sc + OFF_WT);
    // 12. hop-1 heads
    k_small_nt2<<<dim3(BL, 2), 192>>>(sc + OFF_FA1, sc + OFF_FB1, G4,
                                      cls_w, cls_w, G4, G4,
                                      sc + OFF_X1, sc + OFF_Y1);
    // 13. lm1 (cb computed inline from C1; block b==0 publishes CB1 for const2)
    k_lm<<<BATCH * CNUM, 128>>>(sc + OFF_X1, sc + OFF_Y1, sc + OFF_C1, cls_w, cls_b,
                                sc + OFF_LM1, sc + OFF_CB1);

    // 14. hop 2: FA2 = FA1@Wf^T + rank12 ; FB2 analog (full-width Wf both)
    k_gemm_nt_r12<<<dim3(16, 8, 2), tb>>>(sc + OFF_FA1, G4, (long long)(OFF_FB1 - OFF_FA1),
                                          feat_w, 1042, 0,
                                          sc + OFF_FA2, G4, (long long)(OFF_FB2 - OFF_FA2),
                                          G4, sc + OFF_LM1, sc + OFF_X1, sc + OFF_Y1,
                                          sc + OFF_WT);
    // 15. const2
    k_const2<<<128, 256>>>(sc + OFF_C1, feat_w, feat_b, sc + OFF_CB1, sc + OFF_WT, sc + OFF_C2);
    // 16. hop-2 heads
    k_small_nt2<<<dim3(BL, 2), 192>>>(sc + OFF_FA2, sc + OFF_FB2, G4,
                                      cls_w, cls_w, G4, G4,
                                      sc + OFF_X2, sc + OFF_Y2);
    // 17. CB2
    k_cb<<<1, 192>>>(sc + OFF_C2, cls_w, cls_b, sc + OFF_CB2);
    // 18. output
    k_output<<<(BATCH * SEQ * SEQ * CNUM + 255) / 256, 256>>>(sc + OFF_X2, sc + OFF_Y2,
                                                             sc + OFF_CB2, out);
}

// round 8
// speedup vs baseline: 2.3234x; 2.3234x over previous
#include <cuda_runtime.h>
#include <cuda_bf16.h>
#include <math.h>
#include <stdint.h>

// Problem constants
#define BATCH 4
#define SEQ   128
#define HID   256
#define CNUM  6
#define EMBD  400
#define G4    1024
#define D2    512
#define BL    512          // BATCH*SEQ

// ---------------- scratch offsets (floats) ----------------
#define OFF_EMB   0u               // 512*400
#define OFF_XGF   204800u          // 512*1024
#define OFF_XGB   729088u          // 512*1024
#define OFF_CTX   1253376u         // 512*512
#define OFF_Q     1515520u         // 512*512
#define OFF_K     1777664u         // 512*512
#define OFF_S     2039808u         // 4*128*128
#define OFF_CTX2  2105344u         // 512*512
#define OFF_X0    2367488u         // 512*6
#define OFF_Y0    2370560u
#define OFF_LM0   2373632u
#define OFF_FA1   2376704u         // 512*1024
#define OFF_FB1   2900992u         // 512*1024
#define OFF_X1    3425280u
#define OFF_Y1    3428352u
#define OFF_LM1   3431424u
#define OFF_FA2   3434496u         // 512*1024
#define OFF_FB2   3958784u         // 512*1024
#define OFF_X2    4483072u
#define OFF_Y2    4486144u
#define OFF_C1    4489216u         // 1024
#define OFF_C2    4490240u         // 1024
#define OFF_CB1   4491264u         // 8
#define OFF_CB2   4491272u         // 8
#define OFF_WT    4491280u         // 18*1024 packed extra feat_w cols
#define SCRATCH_FLOATS 4509712u

__device__ __align__(16) float g_scratch[SCRATCH_FLOATS];
__device__ unsigned int g_bar[8];

typedef unsigned long long u64;

// ---------------- packed f32x2 helpers (Blackwell FFMA2) ----------------
__device__ __forceinline__ void fma2(u64& d, u64 a, u64 b) {
    asm("fma.rn.f32x2 %0, %1, %2, %0;" : "+l"(d) : "l"(a), "l"(b));
}
__device__ __forceinline__ u64 dupf(float v) {
    u64 r; unsigned u = __float_as_uint(v);
    asm("mov.b64 %0, {%1, %1};" : "=l"(r) : "r"(u));
    return r;
}
__device__ __forceinline__ float2 unpk(u64 v) {
    unsigned lo, hi;
    asm("mov.b64 {%0, %1}, %2;" : "=r"(lo), "=r"(hi) : "l"(v));
    return make_float2(__uint_as_float(lo), __uint_as_float(hi));
}
union F4U { float4 f; u64 u[2]; };
union F2U { float2 f; u64 u; };

__device__ __forceinline__ float sigf(float x) { return 1.f / (1.f + __expf(-x)); }

// ---------------- embedding (+ barrier zero fused) ----------------
__global__ void k_embed(const int* __restrict__ tok, const float* __restrict__ mask,
                        const float* __restrict__ gen, const float* __restrict__ dom,
                        float* __restrict__ emb, unsigned int* __restrict__ bar) {
    if (blockIdx.x == 0 && threadIdx.x < 8) bar[threadIdx.x] = 0u;
    int idx = blockIdx.x * blockDim.x + threadIdx.x;
    if (idx >= BL * EMBD) return;
    int bl = idx / EMBD, d = idx - bl * EMBD;
    int t = tok[bl];
    float v = (d < 300) ? gen[(size_t)t * 300 + d] : dom[(size_t)t * 100 + (d - 300)];
    emb[idx] = v * mask[bl];
}

// ---------------- GEMM NT core, double-buffered, f32x2 inner ----------------
// Optional fused rank-12 epilogue: C[m,n] += sum_c U[m,c]*WT[offU+c][n] + V[m,c]*WT[12+c][n]
__device__ __forceinline__ void gemm_nt_body(
    const float* __restrict__ A, int lda,
    const float* __restrict__ B, int ldb,
    float* __restrict__ C, int ldc, int K,
    const float* __restrict__ b0, const float* __restrict__ b1,
    const float* __restrict__ U, const float* __restrict__ V,
    const float* __restrict__ WT, int offU) {
    __shared__ __align__(16) float As[16][68];
    __shared__ __align__(16) float Bs[16][68];
    const int tx = threadIdx.x, ty = threadIdx.y;
    const int m0 = blockIdx.y * 64, n0 = blockIdx.x * 64;
    u64 acc2[2][4];
#pragma unroll
    for (int p = 0; p < 2; p++)
#pragma unroll
        for (int j = 0; j < 4; j++) acc2[p][j] = 0ull;

    float pa[4], pb[4];
#pragma unroll
    for (int r = 0; r < 4; r++) {
        int m = ty + r * 16;
        pa[r] = A[(size_t)(m0 + m) * lda + tx];
        pb[r] = B[(size_t)(n0 + m) * ldb + tx];
    }
    for (int k0 = 0; k0 < K; k0 += 16) {
#pragma unroll
        for (int r = 0; r < 4; r++) {
            int m = ty + r * 16;
            As[tx][m] = pa[r];
            Bs[tx][m] = pb[r];
        }
        __syncthreads();
        if (k0 + 16 < K) {
#pragma unroll
            for (int r = 0; r < 4; r++) {
                int m = ty + r * 16;
                pa[r] = A[(size_t)(m0 + m) * lda + k0 + 16 + tx];
                pb[r] = B[(size_t)(n0 + m) * ldb + k0 + 16 + tx];
            }
        }
#pragma unroll
        for (int k = 0; k < 16; k++) {
            const ulonglong2 a2 = *(const ulonglong2*)(&As[k][ty * 4]);
            const float4 b4 = *(const float4*)(&Bs[k][tx * 4]);
            u64 bd0 = dupf(b4.x), bd1 = dupf(b4.y), bd2 = dupf(b4.z), bd3 = dupf(b4.w);
            fma2(acc2[0][0], a2.x, bd0); fma2(acc2[0][1], a2.x, bd1);
            fma2(acc2[0][2], a2.x, bd2); fma2(acc2[0][3], a2.x, bd3);
            fma2(acc2[1][0], a2.y, bd0); fma2(acc2[1][1], a2.y, bd1);
            fma2(acc2[1][2], a2.y, bd2); fma2(acc2[1][3], a2.y, bd3);
        }
        __syncthreads();
    }
#pragma unroll
    for (int p = 0; p < 2; p++) {
#pragma unroll
        for (int j = 0; j < 4; j++) {
            float2 v = unpk(acc2[p][j]);
            int n = n0 + tx * 4 + j;
            int m = m0 + ty * 4 + 2 * p;
            float e0 = (b0 ? b0[n] : 0.f) + (b1 ? b1[n] : 0.f);
            float e1 = e0;
            if (WT) {
#pragma unroll
                for (int c = 0; c < CNUM; c++) {
                    float wu = WT[(size_t)(offU + c) * 1024 + n];
                    float wv = WT[(size_t)(12 + c) * 1024 + n];
                    e0 += U[(size_t)m * CNUM + c] * wu + V[(size_t)m * CNUM + c] * wv;
                    e1 += U[(size_t)(m + 1) * CNUM + c] * wu + V[(size_t)(m + 1) * CNUM + c] * wv;
                }
            }
            C[(size_t)m * ldc + n]       = v.x + e0;
            C[(size_t)(m + 1) * ldc + n] = v.y + e1;
        }
    }
}

__global__ void k_gemm_nt(const float* __restrict__ A, int lda, long long sA,
                          const float* __restrict__ B, int ldb, long long sB,
                          float* __restrict__ C, int ldc, long long sC,
                          int K, const float* __restrict__ b0, const float* __restrict__ b1) {
    gemm_nt_body(A + blockIdx.z * sA, lda, B + blockIdx.z * sB, ldb,
                 C + blockIdx.z * sC, ldc, K, b0, b1,
                 nullptr, nullptr, nullptr, 0);
}

__global__ void k_gemm_nt_r12(const float* __restrict__ A, int lda, long long sA,
                              const float* __restrict__ B, int ldb, long long sB,
                              float* __restrict__ C, int ldc, long long sC, int K,
                              const float* __restrict__ U,
                              const float* __restrict__ V0, const float* __restrict__ V1,
                              const float* __restrict__ WT) {
    int z = blockIdx.z;
    gemm_nt_body(A + z * sA, lda, B + z * sB, ldb, C + z * sC, ldc, K,
                 nullptr, nullptr, U, z ? V1 : V0, WT, z ? 6 : 0);
}

__global__ void k_gemm_nt2(const float* __restrict__ A0, const float* __restrict__ A1, int lda,
                           const float* __restrict__ B0, const float* __restrict__ B1, int ldb,
                           float* __restrict__ C0, float* __restrict__ C1, int ldc, int K,
                           const float* __restrict__ p00, const float* __restrict__ p01,
                           const float* __restrict__ p10, const float* __restrict__ p11) {
    if (blockIdx.z == 0)
        gemm_nt_body(A0, lda, B0, ldb, C0, ldc, K, p00, p01, nullptr, nullptr, nullptr, 0);
    else
        gemm_nt_body(A1, lda, B1, ldb, C1, ldc, K, p10, p11, nullptr, nullptr, nullptr, 0);
}

// ---------------- GEMM NN, double-buffered, f32x2 inner ----------------
__global__ void k_gemm_nn(const float* __restrict__ A, int lda, long long sA,
                          const float* __restrict__ B, int ldb, long long sB,
                          float* __restrict__ C, int ldc, long long sC,
                          int K, const float* __restrict__ D, int ldd, long long sD) {
    A += blockIdx.z * sA; B += blockIdx.z * sB; C += blockIdx.z * sC;
    if (D) D += blockIdx.z * sD;
    __shared__ __align__(16) float As[16][68];
    __shared__ __align__(16) float Bs[16][68];
    const int tx = threadIdx.x, ty = threadIdx.y;
    const int t = ty * 16 + tx;
    const int m0 = blockIdx.y * 64, n0 = blockIdx.x * 64;
    const int bn = t & 63, bk = t >> 6;
    u64 acc2[2][4];
#pragma unroll
    for (int p = 0; p < 2; p++)
#pragma unroll
        for (int j = 0; j < 4; j++) acc2[p][j] = 0ull;

    float pa[4], pb[4];
#pragma unroll
    for (int r = 0; r < 4; r++) {
        int m = ty + r * 16;
        pa[r] = A[(size_t)(m0 + m) * lda + tx];
        pb[r] = B[(size_t)(bk + r * 4) * ldb + n0 + bn];
    }
    for (int k0 = 0; k0 < K; k0 += 16) {
#pragma unroll
        for (int r = 0; r < 4; r++) {
            int m = ty + r * 16;
            As[tx][m] = pa[r];
            Bs[bk + r * 4][bn] = pb[r];
        }
        __syncthreads();
        if (k0 + 16 < K) {
#pragma unroll
            for (int r = 0; r < 4; r++) {
                int m = ty + r * 16;
                pa[r] = A[(size_t)(m0 + m) * lda + k0 + 16 + tx];
                pb[r] = B[(size_t)(k0 + 16 + bk + r * 4) * ldb + n0 + bn];
            }
        }
#pragma unroll
        for (int k = 0; k < 16; k++) {
            const ulonglong2 a2 = *(const ulonglong2*)(&As[k][ty * 4]);
            const float4 b4 = *(const float4*)(&Bs[k][tx * 4]);
            u64 bd0 = dupf(b4.x), bd1 = dupf(b4.y), bd2 = dupf(b4.z), bd3 = dupf(b4.w);
            fma2(acc2[0][0], a2.x, bd0); fma2(acc2[0][1], a2.x, bd1);
            fma2(acc2[0][2], a2.x, bd2); fma2(acc2[0][3], a2.x, bd3);
            fma2(acc2[1][0], a2.y, bd0); fma2(acc2[1][1], a2.y, bd1);
            fma2(acc2[1][2], a2.y, bd2); fma2(acc2[1][3], a2.y, bd3);
        }
        __syncthreads();
    }
#pragma unroll
    for (int p = 0; p < 2; p++) {
#pragma unroll
        for (int j = 0; j < 4; j++) {
            float2 v = unpk(acc2[p][j]);
            int n = n0 + tx * 4 + j;
            int m = m0 + ty * 4 + 2 * p;
            float d0 = D ? D[(size_t)m * ldd + n] : 0.f;
            float d1 = D ? D[(size_t)(m + 1) * ldd + n] : 0.f;
            C[(size_t)m * ldc + n]       = v.x + d0;
            C[(size_t)(m + 1) * ldc + n] = v.y + d1;
        }
    }
}

// ---------------- BiLSTM recurrence, weights-in-registers ----------------
// 64 blocks = 8 groups (b,dir) x 8 slices (32 cells). 256 threads:
// tid = cell*8 + type*2 + kc  (cell 0..31, type 0..3 = i,f,g,o, kc 0..1 = k-half).
// Each thread holds whh[type*256+cellg][kc*128 .. +128] in 64 u64 registers.
__global__ void __launch_bounds__(256, 1)
k_lstm(const float* __restrict__ xgf, const float* __restrict__ xgb,
       const float* __restrict__ whhf, const float* __restrict__ whhb,
       float* __restrict__ ctx, unsigned int* __restrict__ bar) {
    const int bx = blockIdx.x;
    const int group = bx >> 3, slice = bx & 7;
    const int b = group >> 1, dir = group & 1;
    const float* xg  = dir ? xgb : xgf;
    const float* whh = dir ? whhb : whhf;
    const int tid = threadIdx.x;
    const int cell = tid >> 3;            // 0..31
    const int type = (tid >> 1) & 3;      // 0..3
    const int kc   = tid & 1;             // 0..1
    const int cellg = slice * 32 + cell;
    const int row = type * 256 + cellg;

    // preload weights into registers: 128 floats = 64 u64
    u64 w[64];
    {
        const float4* wp = (const float4*)(whh + (size_t)row * 256 + kc * 128);
#pragma unroll
        for (int i = 0; i < 32; i++) {
            F4U t4; t4.f = wp[i];
            w[2 * i] = t4.u[0]; w[2 * i + 1] = t4.u[1];
        }
    }

    __shared__ __align__(16) float hs[256];
    __shared__ float xgs[128];
    float c_reg = 0.f;
    volatile unsigned int* cnt = bar + group;
    const bool upd = ((tid & 7) == 0);
    const int lane = tid & 31;
    const int L0 = lane & 24;             // (cell%4)*8

    for (int s = 0; s < SEQ; s++) {
        const int t = dir ? (SEQ - 1 - s) : s;
        // stage h_prev and xg slice
        if (tid < 64) {
            if (s > 0) {
                const int tp = dir ? (t + 1) : (t - 1);
                const float4* hp = (const float4*)(ctx + (size_t)(b * SEQ + tp) * D2 + dir * HID);
                ((float4*)hs)[tid] = __ldcg(hp + tid);
            }
        } else if (tid < 192) {
            int i = tid - 64;             // 0..127: type'=i>>5, cell'=i&31
            xgs[i] = xg[(size_t)(b * SEQ + t) * G4 + (i >> 5) * 256 + slice * 32 + (i & 31)];
        }
        __syncthreads();

        float g = 0.f;
        if (s > 0) {
            u64 a0 = 0ull, a1 = 0ull;
            const float4* hp4 = (const float4*)(hs + kc * 128);
#pragma unroll
            for (int i = 0; i < 32; i++) {
                F4U hv; hv.f = hp4[i];
                fma2(a0, w[2 * i], hv.u[0]);
                fma2(a1, w[2 * i + 1], hv.u[1]);
            }
            float2 r0 = unpk(a0), r1 = unpk(a1);
            g = (r0.x + r0.y) + (r1.x + r1.y);
        }
        g += __shfl_xor_sync(0xffffffffu, g, 1);   // sum the two k-half partial dots
        g += xgs[type * 32 + cell];                 // add xg once (same on both kc lanes)

        // gather i,f,g,o within warp (both kc lanes of each (cell,type) hold the sum)
        float gi = __shfl_sync(0xffffffffu, g, L0 | 0);
        float gf = __shfl_sync(0xffffffffu, g, L0 | 2);
        float gg = __shfl_sync(0xffffffffu, g, L0 | 4);
        float go = __shfl_sync(0xffffffffu, g, L0 | 6);
        if (upd) {
            c_reg = sigf(gf) * c_reg + sigf(gi) * tanhf(gg);
            float h = sigf(go) * tanhf(c_reg);
            ctx[(size_t)(b * SEQ + t) * D2 + dir * HID + cellg] = h;
        }
        __syncthreads();                             // h stores ordered block-wide
        if (tid == 0) {
            __threadfence();                         // cumulative release of block's h stores
            atomicAdd((unsigned int*)(bar + group), 1u);
            unsigned int target = 8u * (unsigned)(s + 1);
            while (*cnt < target) { __nanosleep(64); }
            __threadfence();                         // acquire
        }
        __syncthreads();
    }
}

// ---------------- softmax over keys (row-wise, with mask) ----------------
__global__ void k_softmax(float* __restrict__ S, const float* __restrict__ mask) {
    int rowid = blockIdx.x;              // b*128 + i
    int b = rowid >> 7;
    int j = threadIdx.x;
    __shared__ float sh[128];
    float* row = S + (size_t)rowid * 128;
    float v = row[j];
    if (mask[b * 128 + j] <= 0.f) v = -1e30f;
    sh[j] = v; __syncthreads();
    for (int off = 64; off > 0; off >>= 1) {
        if (j < off) sh[j] = fmaxf(sh[j], sh[j + off]);
        __syncthreads();
    }
    float mx = sh[0]; __syncthreads();
    float e = __expf(v - mx);
    sh[j] = e; __syncthreads();
    for (int off = 64; off > 0; off >>= 1) {
        if (j < off) sh[j] += sh[j + off];
        __syncthreads();
    }
    row[j] = e / sh[0];
}

// ---------------- fused small NT gemm pair ----------------
__global__ void k_small_nt2(const float* __restrict__ A0, const float* __restrict__ A1, int lda,
                            const float* __restrict__ B0, const float* __restrict__ B1, int ldb,
                            int K, float* __restrict__ C0, float* __restrict__ C1) {
    int z = blockIdx.y;
    const float* A = z ? A1 : A0;
    const float* B = z ? B1 : B0;
    float* C = z ? C1 : C0;
    int r = blockIdx.x;
    int c = threadIdx.x >> 5, lane = threadIdx.x & 31;
    if (c >= CNUM) return;
    const float* a = A + (size_t)r * lda;
    const float* w = B + (size_t)c * ldb;
    u64 acc0 = 0ull, acc1 = 0ull;
    for (int k = lane * 2; k < K; k += 128) {
        F2U av, wv; av.f = *(const float2*)(a + k); wv.f = *(const float2*)(w + k);
        fma2(acc0, av.u, wv.u);
        int k2 = k + 64;
        if (k2 < K) {
            F2U av2, wv2; av2.f = *(const float2*)(a + k2); wv2.f = *(const float2*)(w + k2);
            fma2(acc1, av2.u, wv2.u);
        }
    }
    float2 r0 = unpk(acc0), r1 = unpk(acc1);
    float s = (r0.x + r0.y) + (r1.x + r1.y);
#pragma unroll
    for (int off = 16; off > 0; off >>= 1) s += __shfl_xor_sync(0xffffffffu, s, off);
    if (lane == 0) C[(size_t)r * CNUM + c] = s;
}

// ---------------- lm via prefix/suffix max, with inline cb ----------------
__global__ void k_lm(const float* __restrict__ X, const float* __restrict__ Y,
                     const float* __restrict__ vecC, const float* __restrict__ cls_w,
                     const float* __restrict__ cls_b,
                     float* __restrict__ LM, float* __restrict__ CBout) {
    int b = blockIdx.x / CNUM, c = blockIdx.x % CNUM;
    int l = threadIdx.x;
    __shared__ float px[128], sy[128], red[128];
    float cbv = cls_b[c];
    if (vecC) {
        const float* w = cls_w + (size_t)c * 1024;
        float partial = 0.f;
#pragma unroll
        for (int d = l; d < 1024; d += 128) partial += vecC[d] * w[d];
        red[l] = partial; __syncthreads();
        for (int off = 64; off > 0; off >>= 1) {
            if (l < off) red[l] += red[l + off];
            __syncthreads();
        }
        cbv += red[0];
        __syncthreads();
    }
    if (CBout && b == 0 && l == 0) CBout[c] = cbv;
    float x = X[(size_t)(b * 128 + l) * CNUM + c];
    float y = Y[(size_t)(b * 128 + l) * CNUM + c];
    px[l] = x; sy[l] = y;
    __syncthreads();
    for (int off = 1; off < 128; off <<= 1) {
        float pother = (l >= off) ? px[l - off] : -3e38f;
        float sother = (l + off < 128) ? sy[l + off] : -3e38f;
        float pmine = px[l], smine = sy[l];
        __syncthreads();
        px[l] = fmaxf(pmine, pother);
        sy[l] = fmaxf(smine, sother);
        __syncthreads();
    }
    float v = fmaxf(fmaxf(px[l] + y + cbv, x + sy[l] + cbv), 0.f);
    LM[(size_t)(b * 128 + l) * CNUM + c] = v;
}

// ---------------- packWT + const1 fused ----------------
__global__ void k_packWT_c1(const float* __restrict__ fw, float* __restrict__ WT,
                            const float* __restrict__ feat_b, const float* __restrict__ cls_b,
                            float* __restrict__ C1) {
    int bx = blockIdx.x;
    if (bx < 72) {
        int idx = bx * 256 + threadIdx.x;
        if (idx < 18 * 1024) {
            int c = idx >> 10, o = idx & 1023;
            WT[idx] = fw[(size_t)o * 1042 + 1024 + c];
        }
    } else {
        int o = (bx - 72) * 256 + threadIdx.x;
        float s = feat_b[o];
        const float* row = fw + (size_t)o * 1042 + 1036;
#pragma unroll
        for (int c = 0; c < CNUM; c++) s += cls_b[c] * row[c];
        C1[o] = s;
    }
}

// const2[o] = feat_b[o] + dot(C1, feat_w[o,0:1024]) + sum_c CB1[c]*Wp[o,c]
__global__ void k_const2(const float* __restrict__ C1, const float* __restrict__ fw,
                         const float* __restrict__ feat_b, const float* __restrict__ CB1,
                         const float* __restrict__ WT, float* __restrict__ C2) {
    int warp = threadIdx.x >> 5, lane = threadIdx.x & 31;
    int o = blockIdx.x * (blockDim.x >> 5) + warp;
    const float* w = fw + (size_t)o * 1042;
    float s = 0.f;
    for (int d = lane; d < 1024; d += 32) s += C1[d] * w[d];
#pragma unroll
    for (int off = 16; off > 0; off >>= 1) s += __shfl_xor_sync(0xffffffffu, s, off);
    if (lane == 0) {
        float v = feat_b[o] + s;
#pragma unroll
        for (int c = 0; c < CNUM; c++) v += CB1[c] * WT[(size_t)(12 + c) * 1024 + o];
        C2[o] = v;
    }
}

// cb[c] = cls_b[c] + dot(vec[0:1024], cls_w[c,:])
__global__ void k_cb(const float* __restrict__ vec, const float* __restrict__ cls_w,
                     const float* __restrict__ cls_b, float* __restrict__ CB) {
    int c = threadIdx.x >> 5, lane = threadIdx.x & 31;
    if (c >= CNUM) return;
    const float* w = cls_w + (size_t)c * 1024;
    float s = 0.f;
    for (int d = lane; d < 1024; d += 32) s += vec[d] * w[d];
#pragma unroll
    for (int off = 16; off > 0; off >>= 1) s += __shfl_xor_sync(0xffffffffu, s, off);
    if (lane == 0) CB[c] = cls_b[c] + s;
}

// ---------------- final separable write ----------------
__global__ void k_output(const float* __restrict__ X2, const float* __restrict__ Y2,
                         const float* __restrict__ CB2, float* __restrict__ out) {
    int idx = blockIdx.x * blockDim.x + threadIdx.x;
    if (idx >= BATCH * SEQ * SEQ * CNUM) return;
    int c = idx % CNUM;
    int j = (idx / CNUM) & 127;
    int i = (idx / (CNUM * SEQ)) & 127;
    int b = idx / (CNUM * SEQ * SEQ);
    out[idx] = X2[(size_t)(b * 128 + i) * CNUM + c] + Y2[(size_t)(b * 128 + j) * CNUM + c] + CB2[c];
}

// ---------------- launch ----------------
extern "C" void kernel_launch(void* const* d_in, const int* in_sizes, int n_in,
                              void* d_out, int out_size) {
    const int*   tok     = (const int*)  d_in[0];
    const float* mask    = (const float*)d_in[2];
    const float* gen     = (const float*)d_in[3];
    const float* dom     = (const float*)d_in[4];
    const float* wih_f   = (const float*)d_in[5];
    const float* whh_f   = (const float*)d_in[6];
    const float* bih_f   = (const float*)d_in[7];
    const float* bhh_f   = (const float*)d_in[8];
    const float* wih_b   = (const float*)d_in[9];
    const float* whh_b   = (const float*)d_in[10];
    const float* bih_b   = (const float*)d_in[11];
    const float* bhh_b   = (const float*)d_in[12];
    const float* wq      = (const float*)d_in[13];
    const float* bq      = (const float*)d_in[14];
    const float* wk      = (const float*)d_in[15];
    const float* bk      = (const float*)d_in[16];
    const float* feat_w  = (const float*)d_in[17];
    const float* feat_b  = (const float*)d_in[18];
    const float* cls_w   = (const float*)d_in[19];
    const float* cls_b   = (const float*)d_in[20];
    float* out = (float*)d_out;

    float* sc = nullptr;
    unsigned int* bar = nullptr;
    cudaGetSymbolAddress((void**)&sc, g_scratch);
    cudaGetSymbolAddress((void**)&bar, g_bar);

    dim3 tb(16, 16);

    k_embed<<<(BL * EMBD + 255) / 256, 256>>>(tok, mask, gen, dom, sc + OFF_EMB, bar);

    k_gemm_nt2<<<dim3(16, 8, 2), tb>>>(sc + OFF_EMB, sc + OFF_EMB, EMBD,
                                       wih_f, wih_b, EMBD,
                                       sc + OFF_XGF, sc + OFF_XGB, G4, EMBD,
                                       bih_f, bhh_f, bih_b, bhh_b);

    k_lstm<<<64, 256>>>(sc + OFF_XGF, sc + OFF_XGB, whh_f, whh_b, sc + OFF_CTX, bar);

    k_gemm_nt2<<<dim3(8, 8, 2), tb>>>(sc + OFF_CTX, sc + OFF_CTX, D2,
                                      wq, wk, D2,
                                      sc + OFF_Q, sc + OFF_K, D2, D2,
                                      bq, nullptr, bk, nullptr);
    k_gemm_nt<<<dim3(2, 2, 4), tb>>>(sc + OFF_Q, D2, 65536, sc + OFF_K, D2, 65536,
                                     sc + OFF_S, 128, 16384, D2, nullptr, nullptr);
    k_softmax<<<BL, 128>>>(sc + OFF_S, mask);
    k_gemm_nn<<<dim3(8, 2, 4), tb>>>(sc + OFF_S, 128, 16384, sc + OFF_CTX, D2, 65536,
                                     sc + OFF_CTX2, D2, 65536, 128,
                                     sc + OFF_CTX, D2, 65536);

    k_small_nt2<<<dim3(BL, 2), 192>>>(sc + OFF_CTX2, sc + OFF_CTX2, D2,
                                      cls_w, cls_w + 512, G4, D2,
                                      sc + OFF_X0, sc + OFF_Y0);
    k_lm<<<BATCH * CNUM, 128>>>(sc + OFF_X0, sc + OFF_Y0, nullptr, cls_w, cls_b,
                                sc + OFF_LM0, nullptr);
    k_packWT_c1<<<76, 256>>>(feat_w, sc + OFF_WT, feat_b, cls_b, sc + OFF_C1);

    k_gemm_nt_r12<<<dim3(16, 8, 2), tb>>>(sc + OFF_CTX2, D2, 0,
                                          feat_w, 1042, 512,
                                          sc + OFF_FA1, G4, (long long)(OFF_FB1 - OFF_FA1),
                                          D2, sc + OFF_LM0, sc + OFF_X0, sc + OFF_Y0,
                                          sc + OFF_WT);
    k_small_nt2<<<dim3(BL, 2), 192>>>(sc + OFF_FA1, sc + OFF_FB1, G4,
                                      cls_w, cls_w, G4, G4,
                                      sc + OFF_X1, sc + OFF_Y1);
    k_lm<<<BATCH * CNUM, 128>>>(sc + OFF_X1, sc + OFF_Y1, sc + OFF_C1, cls_w, cls_b,
                                sc + OFF_LM1, sc + OFF_CB1);

    k_gemm_nt_r12<<<dim3(16, 8, 2), tb>>>(sc + OFF_FA1, G4, (long long)(OFF_FB1 - OFF_FA1),
                                          feat_w, 1042, 0,
                                          sc + OFF_FA2, G4, (long long)(OFF_FB2 - OFF_FA2),
                                          G4, sc + OFF_LM1, sc + OFF_X1, sc + OFF_Y1,
                                          sc + OFF_WT);
    k_const2<<<128, 256>>>(sc + OFF_C1, feat_w, feat_b, sc + OFF_CB1, sc + OFF_WT, sc + OFF_C2);
    k_small_nt2<<<dim3(BL, 2), 192>>>(sc + OFF_FA2, sc + OFF_FB2, G4,
                                      cls_w, cls_w, G4, G4,
                                      sc + OFF_X2, sc + OFF_Y2);
    k_cb<<<1, 192>>>(sc + OFF_C2, cls_w, cls_b, sc + OFF_CB2);

    k_output<<<(BATCH * SEQ * SEQ * CNUM + 255) / 256, 256>>>(sc + OFF_X2, sc + OFF_Y2,
                                                             sc + OFF_CB2, out);
}